// round 1
// baseline (speedup 1.0000x reference)
#include <cuda_runtime.h>
#include <cuda_bf16.h>

// Per-element activation select, branchless.
// Every transcendental path collapses to ONE exp with a code-selected
// argument t, plus one fast reciprocal R = 1/(1+exp(t)):
//   code 0 relu   : max(x, 0)
//   code 1 sigmoid: R                 with t = -x
//   code 2 tanh   : 2R - 1            with t = -2x
//   code 3 elu    : x>0 ? x : E-1     with t =  x       (E = exp(t))
//   code 4 leaky  : max(x, 0.01x)
//   code 5 gelu   : x * R             with t = -2*0.7978845608*(x + 0.044715 x^3)
__device__ __forceinline__ float apply_act(float v, int code) {
    // gelu inner argument: -2 * sqrt(2/pi) * x * (1 + 0.044715 x^2)
    float x2 = v * v;
    float ga = v * fmaf(0.044715f, x2, 1.0f) * (-1.5957691216057308f);

    float t = v;                      // default (covers elu; harmless otherwise)
    if (code == 1) t = -v;
    if (code == 2) t = -2.0f * v;
    if (code == 5) t = ga;

    float E = __expf(t);                         // 1 MUFU (ex2.approx + scale)
    float R = __fdividef(1.0f, 1.0f + E);        // 1 MUFU (rcp.approx)

    float r = fmaxf(v, 0.0f);                    // code 0 (relu)
    if (code == 1) r = R;                        // sigmoid
    if (code == 2) r = fmaf(2.0f, R, -1.0f);     // tanh
    if (code == 3) r = (v > 0.0f) ? v : (E - 1.0f); // elu
    if (code == 4) r = fmaxf(v, 0.01f * v);      // leaky_relu (valid for all x)
    if (code == 5) r = v * R;                    // gelu (tanh approx form)
    return r;
}

// Each thread owns 4 consecutive columns (one float4 / int4 of codes) and
// iterates over all B rows. Codes hit DRAM/L2 exactly once per thread instead
// of once per (row, thread): saves ~100 MB of L2 traffic vs the naive map,
// and hoists the code decode out of the row loop.
__global__ __launch_bounds__(256) void act_select_kernel(
    const float4* __restrict__ x, const int4* __restrict__ codes,
    float4* __restrict__ out, int ncols4, int B)
{
    int c4 = blockIdx.x * blockDim.x + threadIdx.x;
    if (c4 >= ncols4) return;

    const int4 cd = codes[c4];

    #pragma unroll 4
    for (int b = 0; b < B; b++) {
        int idx = b * ncols4 + c4;           // max ~6.4M, fits int
        float4 v = x[idx];
        float4 r;
        r.x = apply_act(v.x, cd.x);
        r.y = apply_act(v.y, cd.y);
        r.z = apply_act(v.z, cd.z);
        r.w = apply_act(v.w, cd.w);
        out[idx] = r;
    }
}

// Scalar fallback (only used if N is not a multiple of 4 — not expected here).
__global__ __launch_bounds__(256) void act_select_scalar(
    const float* __restrict__ x, const int* __restrict__ codes,
    float* __restrict__ out, int N, int B)
{
    int c = blockIdx.x * blockDim.x + threadIdx.x;
    if (c >= N) return;
    int code = codes[c];
    for (int b = 0; b < B; b++) {
        long idx = (long)b * N + c;
        out[idx] = apply_act(x[idx], code);
    }
}

extern "C" void kernel_launch(void* const* d_in, const int* in_sizes, int n_in,
                              void* d_out, int out_size) {
    const float* x     = (const float*)d_in[0];
    const int*   codes = (const int*)d_in[1];
    float*       out   = (float*)d_out;

    int total = in_sizes[0];      // B * N
    int N     = in_sizes[1];      // C*H*W
    int B     = total / N;

    const int threads = 256;
    if ((N & 3) == 0) {
        int ncols4 = N >> 2;
        int blocks = (ncols4 + threads - 1) / threads;
        act_select_kernel<<<blocks, threads>>>(
            (const float4*)x, (const int4*)codes, (float4*)out, ncols4, B);
    } else {
        int blocks = (N + threads - 1) / threads;
        act_select_scalar<<<blocks, threads>>>(x, codes, out, N, B);
    }
}

// round 3
// speedup vs baseline: 1.4367x; 1.4367x over previous
#include <cuda_runtime.h>
#include <cuda_bf16.h>

// Per-element activation select, branchless.
// Every transcendental path collapses to ONE exp with a code-selected
// argument t, plus one fast reciprocal R = 1/(1+exp(t)):
//   code 0 relu   : max(v, 0)
//   code 1 sigmoid: R                   with t = -v
//   code 2 tanh   : 2R - 1              with t = -2v
//   code 3 elu    : max(v,0)+min(E-1,0) with t =  v      (E = exp(t))
//   code 4 leaky  : max(v, 0.01v)
//   code 5 gelu   : v * R               with t = -2*0.7978845608*(v + 0.044715 v^3)
__device__ __forceinline__ float apply_act(float v, int code) {
    float x2 = v * v;
    float ga = v * fmaf(0.044715f, x2, 1.0f) * (-1.5957691216057308f);

    float t = v;                                  // elu default
    if (code == 1) t = -v;
    if (code == 2) t = -2.0f * v;
    if (code == 5) t = ga;

    float E = __expf(t);                          // MUFU ex2
    float R = __fdividef(1.0f, 1.0f + E);         // MUFU rcp

    // relu / leaky share one fmaxf; slope select is loop-invariant per column
    float r = fmaxf(v, (code == 4) ? 0.01f * v : 0.0f);
    if (code == 1) r = R;
    if (code == 2) r = fmaf(2.0f, R, -1.0f);
    if (code == 3) r = fmaxf(v, 0.0f) + fminf(E - 1.0f, 0.0f);  // branch-free elu
    if (code == 5) r = v * R;
    return r;
}

// Grid: x over column-chunks (float4 granularity), y over row groups of ROWS.
// Loads are front-batched into registers (MLP = ROWS x LDG.128) so DRAM
// latency is covered with modest occupancy; codes are loaded once per thread.
template<int ROWS>
__global__ __launch_bounds__(256) void act_select_rows(
    const float4* __restrict__ x, const int4* __restrict__ codes,
    float4* __restrict__ out, int ncols4)
{
    int c4 = blockIdx.x * blockDim.x + threadIdx.x;
    if (c4 >= ncols4) return;

    const int4 cd = codes[c4];
    int base = blockIdx.y * ROWS * ncols4 + c4;

    float4 v[ROWS];
    #pragma unroll
    for (int r = 0; r < ROWS; r++)
        v[r] = x[base + r * ncols4];

    #pragma unroll
    for (int r = 0; r < ROWS; r++) {
        float4 o;
        o.x = apply_act(v[r].x, cd.x);
        o.y = apply_act(v[r].y, cd.y);
        o.z = apply_act(v[r].z, cd.z);
        o.w = apply_act(v[r].w, cd.w);
        out[base + r * ncols4] = o;
    }
}

// Scalar fallback (N not divisible by 4, or leftover rows) — not expected here.
__global__ __launch_bounds__(256) void act_select_scalar(
    const float* __restrict__ x, const int* __restrict__ codes,
    float* __restrict__ out, int N, int b_begin, int b_end)
{
    int c = blockIdx.x * blockDim.x + threadIdx.x;
    if (c >= N) return;
    int code = codes[c];
    for (int b = b_begin; b < b_end; b++) {
        long idx = (long)b * N + c;
        out[idx] = apply_act(x[idx], code);
    }
}

extern "C" void kernel_launch(void* const* d_in, const int* in_sizes, int n_in,
                              void* d_out, int out_size) {
    const float* x     = (const float*)d_in[0];
    const int*   codes = (const int*)d_in[1];
    float*       out   = (float*)d_out;

    int total = in_sizes[0];      // B * N
    int N     = in_sizes[1];      // C*H*W
    int B     = total / N;

    const int threads = 256;
    constexpr int ROWS = 4;

    if ((N & 3) == 0 && B >= ROWS) {
        int ncols4 = N >> 2;
        int bx = (ncols4 + threads - 1) / threads;
        int by = B / ROWS;
        dim3 grid(bx, by);
        act_select_rows<ROWS><<<grid, threads>>>(
            (const float4*)x, (const int4*)codes, (float4*)out, ncols4);
        int rem = B - by * ROWS;
        if (rem > 0) {
            int blocks = (N + threads - 1) / threads;
            act_select_scalar<<<blocks, threads>>>(x, codes, out, N, by * ROWS, B);
        }
    } else {
        int blocks = (N + threads - 1) / threads;
        act_select_scalar<<<blocks, threads>>>(x, codes, out, N, 0, B);
    }
}

// round 9
// speedup vs baseline: 1.6027x; 1.1156x over previous
#include <cuda_runtime.h>
#include <cuda_bf16.h>

// Per-code coefficient table (constant memory). Every activation is:
//   t = v * (G*v^2 + A)            (A, G pre-scaled by log2(e))
//   E = 2^t,  R = 1/(1+E)
//   r = m*max(v, s*v) + p*R + d*(v*R) + e*min(E-1, 0) + q
//
// code 0 relu   : m=1
// code 1 sigmoid: p=1, A=-log2e           -> R = 1/(1+e^-v)
// code 2 tanh   : p=2, q=-1, A=-2log2e    -> 2R-1
// code 3 elu    : m=1, e=1, A=+log2e      -> max(v,0)+min(e^v-1,0)
// code 4 leaky  : m=1, s=0.01
// code 5 gelu   : d=1, cubic: t = -2*log2e*0.79788456*(v + 0.044715 v^3)
#define LOG2E 1.4426950408889634f
__constant__ float4 COEF1[6] = {   // {s, A, G, m}
    {0.0f,  0.0f,           0.0f,           1.0f},  // relu
    {0.0f, -LOG2E,          0.0f,           0.0f},  // sigmoid
    {0.0f, -2.0f*LOG2E,     0.0f,           0.0f},  // tanh
    {0.0f,  LOG2E,          0.0f,           1.0f},  // elu
    {0.01f, 0.0f,           0.0f,           1.0f},  // leaky
    {0.0f, -2.3022082299f,  -0.1029432431f, 0.0f},  // gelu
};
__constant__ float4 COEF2[6] = {   // {p, q, d, e}
    {0.0f,  0.0f, 0.0f, 0.0f},   // relu
    {1.0f,  0.0f, 0.0f, 0.0f},   // sigmoid
    {2.0f, -1.0f, 0.0f, 0.0f},   // tanh
    {0.0f,  0.0f, 0.0f, 1.0f},   // elu
    {0.0f,  0.0f, 0.0f, 0.0f},   // leaky
    {0.0f,  0.0f, 1.0f, 0.0f},   // gelu
};

__device__ __forceinline__ float act_eval(float v, float4 c1, float4 c2) {
    float vv = v * v;
    float t  = v * fmaf(c1.z, vv, c1.y);            // cubic argument, log2-scaled
    float E;  asm("ex2.approx.ftz.f32 %0, %1;" : "=f"(E) : "f"(t));
    float den = 1.0f + E;
    float R;  asm("rcp.approx.ftz.f32 %0, %1;" : "=f"(R) : "f"(den));
    float mx = fmaxf(v, c1.x * v);                  // relu / leaky
    float mn = fminf(E - 1.0f, 0.0f);               // elu negative branch
    float r  = fmaf(c2.w, mn, c2.y);                // e*mn + q
    r = fmaf(c2.z, v * R, r);                       // + d*(v*R)
    r = fmaf(c2.x, R, r);                           // + p*R
    r = fmaf(c1.w, mx, r);                          // + m*mx
    return r;
}

// Grid: x over float2 column pairs, y over groups of ROWS rows.
// Coefficients decoded ONCE per column (outside the row loop); the inner loop
// is pure FMA/MUFU with zero predicates. Loads front-batched -> MLP_p1 = 8.
constexpr int ROWS = 8;

__global__ __launch_bounds__(256) void act_rows(
    const float2* __restrict__ x, const int2* __restrict__ codes,
    float2* __restrict__ out, int ncols2)
{
    int c = blockIdx.x * blockDim.x + threadIdx.x;
    if (c >= ncols2) return;

    const int2 cd = __ldg(&codes[c]);
    const float4 a1 = COEF1[cd.x], a2 = COEF2[cd.x];
    const float4 b1 = COEF1[cd.y], b2 = COEF2[cd.y];

    int base = blockIdx.y * ROWS * ncols2 + c;

    float2 v[ROWS];
    #pragma unroll
    for (int r = 0; r < ROWS; r++)
        v[r] = x[base + r * ncols2];

    #pragma unroll
    for (int r = 0; r < ROWS; r++) {
        float2 o;
        o.x = act_eval(v[r].x, a1, a2);
        o.y = act_eval(v[r].y, b1, b2);
        out[base + r * ncols2] = o;
    }
}

// Generic fallback (odd N, leftover rows).
__global__ __launch_bounds__(256) void act_scalar(
    const float* __restrict__ x, const int* __restrict__ codes,
    float* __restrict__ out, int N, int b_begin, int b_end)
{
    int c = blockIdx.x * blockDim.x + threadIdx.x;
    if (c >= N) return;
    int code = codes[c];
    const float4 c1 = COEF1[code], c2 = COEF2[code];
    for (int b = b_begin; b < b_end; b++) {
        long idx = (long)b * N + c;
        out[idx] = act_eval(x[idx], c1, c2);
    }
}

extern "C" void kernel_launch(void* const* d_in, const int* in_sizes, int n_in,
                              void* d_out, int out_size) {
    const float* x     = (const float*)d_in[0];
    const int*   codes = (const int*)d_in[1];
    float*       out   = (float*)d_out;

    int total = in_sizes[0];      // B * N
    int N     = in_sizes[1];      // C*H*W
    int B     = total / N;

    const int threads = 256;

    if ((N & 1) == 0 && B >= ROWS) {
        int ncols2 = N >> 1;
        int bx = (ncols2 + threads - 1) / threads;
        int by = B / ROWS;
        dim3 grid(bx, by);
        act_rows<<<grid, threads>>>(
            (const float2*)x, (const int2*)codes, (float2*)out, ncols2);
        int done = by * ROWS;
        if (done < B) {
            int blocks = (N + threads - 1) / threads;
            act_scalar<<<blocks, threads>>>(x, codes, out, N, done, B);
        }
    } else {
        int blocks = (N + threads - 1) / threads;
        act_scalar<<<blocks, threads>>>(x, codes, out, N, 0, B);
    }
}